// round 2
// baseline (speedup 1.0000x reference)
#include <cuda_runtime.h>
#include <cuda_bf16.h>
#include <math_constants.h>

// Problem constants (from reference setup_inputs)
#define MAXN 50000
#define MAXE 800000
#define MAXE2 (MAXN + MAXE)
#define IN_DIM 128
#define F1 128      // H1*HID = 2*64
#define HID 64
#define OUT_DIM 32

// ---------------- scratch (static device globals; no allocation) ----------------
__device__ float g_h1[(size_t)MAXN * F1];     // layer1 pre-aggregation features (x@W1)
__device__ float g_hr[(size_t)MAXN * F1];     // layer1 output after softmax-agg + relu
__device__ float g_h2[(size_t)MAXN * OUT_DIM];// layer2 pre-aggregation features
__device__ float g_as1[MAXN * 2];
__device__ float g_ad1[MAXN * 2];
__device__ float g_as2[MAXN];
__device__ float g_ad2[MAXN];
__device__ int   g_cnt[MAXN];
__device__ int   g_fill[MAXN];
__device__ int   g_rowptr[MAXN + 1];
__device__ int   g_col[MAXE2];                // src node id, edges sorted by dst

// ---------------- kernel 0: zero counters ----------------
__global__ void zero_kernel(int N) {
    int i = blockIdx.x * blockDim.x + threadIdx.x;
    if (i < N) { g_cnt[i] = 0; g_fill[i] = 0; }
}

// ---------------- kernel 1: h1 = x@W1, plus per-node attention dots ----------------
// Block: 256 threads, tile = 32 rows x 128 cols. x tile staged in smem (16KB),
// W1 (64KB) read through L1 via LDG (fully L1-resident after warmup within launch).
#define G1_ROWS 32
__global__ void gemm1_kernel(const float* __restrict__ x, const float* __restrict__ W1,
                             const float* __restrict__ attS, const float* __restrict__ attD,
                             int N) {
    __shared__ float xs[G1_ROWS * 128];
    int row0 = blockIdx.x * G1_ROWS;
    int tid = threadIdx.x;
    // stage x tile (float4-coalesced, zero-padded)
    for (int i = tid; i < G1_ROWS * 128 / 4; i += 256) {
        int elt = i * 4;
        int r = elt >> 7;            // /128
        int c = elt & 127;
        int gr = row0 + r;
        float4 v = make_float4(0.f, 0.f, 0.f, 0.f);
        if (gr < N) v = *(const float4*)(x + (size_t)gr * 128 + c);
        *(float4*)(xs + elt) = v;
    }
    __syncthreads();

    int lane = tid & 31;
    int ry = tid >> 5;               // 8 warps x 4 rows = 32 rows
    const float* Wc = W1 + lane * 4;
    const float* xr = xs + (ry * 4) * 128;

    float4 a0 = make_float4(0,0,0,0), a1 = a0, a2 = a0, a3 = a0;
    #pragma unroll 4
    for (int k = 0; k < 128; k++) {
        float4 w = __ldg((const float4*)(Wc + (size_t)k * 128));
        float x0 = xr[k], x1 = xr[128 + k], x2 = xr[256 + k], x3 = xr[384 + k];
        a0.x += x0 * w.x; a0.y += x0 * w.y; a0.z += x0 * w.z; a0.w += x0 * w.w;
        a1.x += x1 * w.x; a1.y += x1 * w.y; a1.z += x1 * w.z; a1.w += x1 * w.w;
        a2.x += x2 * w.x; a2.y += x2 * w.y; a2.z += x2 * w.z; a2.w += x2 * w.w;
        a3.x += x3 * w.x; a3.y += x3 * w.y; a3.z += x3 * w.z; a3.w += x3 * w.w;
    }

    float4 s4 = __ldg((const float4*)(attS + lane * 4));
    float4 d4 = __ldg((const float4*)(attD + lane * 4));
    float4 accs[4] = {a0, a1, a2, a3};
    #pragma unroll
    for (int r = 0; r < 4; r++) {
        int gr = row0 + ry * 4 + r;
        if (gr >= N) continue;
        float4 a = accs[r];
        *(float4*)(g_h1 + (size_t)gr * 128 + lane * 4) = a;
        float ps = a.x * s4.x + a.y * s4.y + a.z * s4.z + a.w * s4.w;
        float pd = a.x * d4.x + a.y * d4.y + a.z * d4.z + a.w * d4.w;
        // segmented reduce: lanes 0-15 = head0 (cols 0-63), lanes 16-31 = head1
        #pragma unroll
        for (int off = 8; off > 0; off >>= 1) {
            ps += __shfl_down_sync(0xffffffffu, ps, off, 16);
            pd += __shfl_down_sync(0xffffffffu, pd, off, 16);
        }
        if (lane == 0)  { g_as1[gr * 2 + 0] = ps; g_ad1[gr * 2 + 0] = pd; }
        if (lane == 16) { g_as1[gr * 2 + 1] = ps; g_ad1[gr * 2 + 1] = pd; }
    }
}

// ---------------- kernel 2: dst histogram ----------------
__global__ void hist_kernel(const int* __restrict__ ei, int N, int E) {
    int e = blockIdx.x * blockDim.x + threadIdx.x;
    int E2 = E + N;
    if (e < E2) {
        int d = (e < E) ? ei[E + e] : (e - E);
        atomicAdd(&g_cnt[d], 1);
    }
}

// ---------------- kernel 3: exclusive scan -> rowptr (single block) ----------------
__global__ void scan_kernel(int N) {
    __shared__ int warp_sums[32];
    __shared__ int carry_s;
    int tid = threadIdx.x;
    int lane = tid & 31, wid = tid >> 5;
    if (tid == 0) { carry_s = 0; g_rowptr[0] = 0; }
    __syncthreads();
    for (int base = 0; base < N; base += 1024) {
        int i = base + tid;
        int v = (i < N) ? g_cnt[i] : 0;
        int xv = v;
        #pragma unroll
        for (int off = 1; off < 32; off <<= 1) {
            int y = __shfl_up_sync(0xffffffffu, xv, off);
            if (lane >= off) xv += y;
        }
        if (lane == 31) warp_sums[wid] = xv;
        __syncthreads();
        if (wid == 0) {
            int s = warp_sums[lane];
            #pragma unroll
            for (int off = 1; off < 32; off <<= 1) {
                int y = __shfl_up_sync(0xffffffffu, s, off);
                if (lane >= off) s += y;
            }
            warp_sums[lane] = s;
        }
        __syncthreads();
        int pre = (wid > 0) ? warp_sums[wid - 1] : 0;
        int incl = xv + pre + carry_s;
        if (i < N) g_rowptr[i + 1] = incl;
        __syncthreads();
        if (tid == 1023) carry_s = incl;
        __syncthreads();
    }
}

// ---------------- kernel 4: scatter edges into CSR (by dst) ----------------
__global__ void scatter_kernel(const int* __restrict__ ei, int N, int E) {
    int e = blockIdx.x * blockDim.x + threadIdx.x;
    int E2 = E + N;
    if (e < E2) {
        int s, d;
        if (e < E) { s = ei[e]; d = ei[E + e]; }
        else       { s = e - E; d = s; }
        int slot = g_rowptr[d] + atomicAdd(&g_fill[d], 1);
        g_col[slot] = s;
    }
}

// ---------------- kernel 5: layer-1 softmax aggregation (warp per dst) ----------------
__global__ void agg1_kernel(const float* __restrict__ bias1, int N) {
    int wid = threadIdx.x >> 5;
    int lane = threadIdx.x & 31;
    int d = blockIdx.x * 8 + wid;
    if (d >= N) return;
    int p0 = g_rowptr[d], p1 = g_rowptr[d + 1];

    float2 adv = *(const float2*)(g_ad1 + d * 2);
    float my_ad = (lane < 16) ? adv.x : adv.y;

    float m = -1e30f, den = 0.f;
    float4 acc = make_float4(0,0,0,0);
    for (int e = p0; e < p1; e++) {
        int s = g_col[e];
        float2 asv = *(const float2*)(g_as1 + s * 2);
        float logit = ((lane < 16) ? asv.x : asv.y) + my_ad;
        logit = (logit > 0.f) ? logit : 0.2f * logit;
        float mnew = fmaxf(m, logit);
        float scale = __expf(m - mnew);
        float ev = __expf(logit - mnew);
        float4 hv = *(const float4*)(g_h1 + (size_t)s * 128 + lane * 4);
        den = den * scale + ev;
        acc.x = acc.x * scale + ev * hv.x;
        acc.y = acc.y * scale + ev * hv.y;
        acc.z = acc.z * scale + ev * hv.z;
        acc.w = acc.w * scale + ev * hv.w;
        m = mnew;
    }
    float inv = 1.f / (den + 1e-16f);
    float4 b = __ldg((const float4*)(bias1 + lane * 4));
    float4 o;
    o.x = fmaxf(acc.x * inv + b.x, 0.f);
    o.y = fmaxf(acc.y * inv + b.y, 0.f);
    o.z = fmaxf(acc.z * inv + b.z, 0.f);
    o.w = fmaxf(acc.w * inv + b.w, 0.f);
    *(float4*)(g_hr + (size_t)d * 128 + lane * 4) = o;
}

// ---------------- kernel 6: h2 = hr@W2, plus attention dots (H=1,C=32) ----------------
__global__ void gemm2_kernel(const float* __restrict__ W2,
                             const float* __restrict__ attS2, const float* __restrict__ attD2,
                             int N) {
    __shared__ float W2s[128 * 32];
    int tid = threadIdx.x;
    for (int i = tid; i < 128 * 32 / 4; i += 256)
        ((float4*)W2s)[i] = __ldg(((const float4*)W2) + i);
    __syncthreads();

    int lane = tid & 31, wid = tid >> 5;
    int row = blockIdx.x * 8 + wid;
    if (row >= N) return;
    const float* hr = g_hr + (size_t)row * 128;
    float f0 = hr[lane], f1 = hr[32 + lane], f2 = hr[64 + lane], f3 = hr[96 + lane];
    float acc = 0.f;
    #pragma unroll
    for (int k = 0; k < 32; k++) {
        acc += __shfl_sync(0xffffffffu, f0, k) * W2s[k * 32 + lane];
        acc += __shfl_sync(0xffffffffu, f1, k) * W2s[(k + 32) * 32 + lane];
        acc += __shfl_sync(0xffffffffu, f2, k) * W2s[(k + 64) * 32 + lane];
        acc += __shfl_sync(0xffffffffu, f3, k) * W2s[(k + 96) * 32 + lane];
    }
    g_h2[(size_t)row * 32 + lane] = acc;
    float ps = acc * __ldg(attS2 + lane);
    float pd = acc * __ldg(attD2 + lane);
    #pragma unroll
    for (int off = 16; off > 0; off >>= 1) {
        ps += __shfl_down_sync(0xffffffffu, ps, off);
        pd += __shfl_down_sync(0xffffffffu, pd, off);
    }
    if (lane == 0) { g_as2[row] = ps; g_ad2[row] = pd; }
}

// ---------------- kernel 7: layer-2 softmax aggregation (warp per dst) ----------------
__global__ void agg2_kernel(const float* __restrict__ bias2, float* __restrict__ out, int N) {
    int wid = threadIdx.x >> 5;
    int lane = threadIdx.x & 31;
    int d = blockIdx.x * 8 + wid;
    if (d >= N) return;
    int p0 = g_rowptr[d], p1 = g_rowptr[d + 1];
    float add = g_ad2[d];

    float m = -1e30f, den = 0.f, acc = 0.f;
    for (int e = p0; e < p1; e++) {
        int s = g_col[e];
        float logit = g_as2[s] + add;
        logit = (logit > 0.f) ? logit : 0.2f * logit;
        float mnew = fmaxf(m, logit);
        float scale = __expf(m - mnew);
        float ev = __expf(logit - mnew);
        float hv = g_h2[(size_t)s * 32 + lane];
        den = den * scale + ev;
        acc = acc * scale + ev * hv;
        m = mnew;
    }
    out[(size_t)d * 32 + lane] = acc / (den + 1e-16f) + __ldg(bias2 + lane);
}

// ---------------- launch ----------------
extern "C" void kernel_launch(void* const* d_in, const int* in_sizes, int n_in,
                              void* d_out, int out_size) {
    const float* x      = (const float*)d_in[0];
    const int*   ei     = (const int*)  d_in[1];
    const float* W1     = (const float*)d_in[2];
    const float* attS1  = (const float*)d_in[3];
    const float* attD1  = (const float*)d_in[4];
    const float* bias1  = (const float*)d_in[5];
    const float* W2     = (const float*)d_in[6];
    const float* attS2  = (const float*)d_in[7];
    const float* attD2  = (const float*)d_in[8];
    const float* bias2  = (const float*)d_in[9];
    float* out = (float*)d_out;

    int N = in_sizes[0] / IN_DIM;
    int E = in_sizes[1] / 2;
    int E2 = E + N;

    zero_kernel<<<(N + 255) / 256, 256>>>(N);
    gemm1_kernel<<<(N + G1_ROWS - 1) / G1_ROWS, 256>>>(x, W1, attS1, attD1, N);
    hist_kernel<<<(E2 + 255) / 256, 256>>>(ei, N, E);
    scan_kernel<<<1, 1024>>>(N);
    scatter_kernel<<<(E2 + 255) / 256, 256>>>(ei, N, E);
    agg1_kernel<<<(N + 7) / 8, 256>>>(bias1, N);
    gemm2_kernel<<<(N + 7) / 8, 256>>>(W2, attS2, attD2, N);
    agg2_kernel<<<(N + 7) / 8, 256>>>(bias2, out, N);
}

// round 4
// speedup vs baseline: 1.1572x; 1.1572x over previous
#include <cuda_runtime.h>
#include <cuda_fp16.h>
#include <cuda_bf16.h>
#include <math_constants.h>

// Problem constants (from reference setup_inputs)
#define MAXN 50000
#define MAXE 800000
#define MAXE2 (MAXN + MAXE)
#define IN_DIM 128
#define F1 128      // H1*HID = 2*64
#define HID 64
#define OUT_DIM 32
#define SCAN_B 1024
#define NBLK ((MAXN + SCAN_B - 1) / SCAN_B)

// ---------------- scratch (static device globals; no allocation) ----------------
__device__ __half g_h1h[(size_t)MAXN * F1];   // layer1 pre-agg features (x@W1), fp16
__device__ float g_hr[(size_t)MAXN * F1];     // layer1 output after softmax-agg + relu
__device__ float g_h2[(size_t)MAXN * OUT_DIM];// layer2 pre-aggregation features
__device__ float g_as1[MAXN * 2];
__device__ float g_ad1[MAXN * 2];
__device__ float g_as2[MAXN];
__device__ float g_ad2[MAXN];
__device__ int   g_cnt[MAXN];
__device__ int   g_fill[MAXN];
__device__ int   g_rowptr[MAXN + 1];
__device__ int   g_bsum[NBLK + 1];
__device__ int   g_col[MAXE2];                // src node id, edges grouped by dst

// ---------------- kernel 0: zero counters ----------------
__global__ void zero_kernel(int N) {
    int i = blockIdx.x * blockDim.x + threadIdx.x;
    if (i < N) { g_cnt[i] = 0; g_fill[i] = 0; }
    if (i == 0) g_rowptr[0] = 0;
}

// ---------------- kernel 1: h1 = x@W1 (fp16 out), plus per-node attention dots ----------------
#define G1_ROWS 32
__global__ void gemm1_kernel(const float* __restrict__ x, const float* __restrict__ W1,
                             const float* __restrict__ attS, const float* __restrict__ attD,
                             int N) {
    __shared__ float xs[G1_ROWS * 128];
    int row0 = blockIdx.x * G1_ROWS;
    int tid = threadIdx.x;
    for (int i = tid; i < G1_ROWS * 128 / 4; i += 256) {
        int elt = i * 4;
        int r = elt >> 7;
        int c = elt & 127;
        int gr = row0 + r;
        float4 v = make_float4(0.f, 0.f, 0.f, 0.f);
        if (gr < N) v = *(const float4*)(x + (size_t)gr * 128 + c);
        *(float4*)(xs + elt) = v;
    }
    __syncthreads();

    int lane = tid & 31;
    int ry = tid >> 5;
    const float* Wc = W1 + lane * 4;
    const float* xr = xs + (ry * 4) * 128;

    float4 a0 = make_float4(0,0,0,0), a1 = a0, a2 = a0, a3 = a0;
    #pragma unroll 4
    for (int k = 0; k < 128; k++) {
        float4 w = __ldg((const float4*)(Wc + (size_t)k * 128));
        float x0 = xr[k], x1 = xr[128 + k], x2 = xr[256 + k], x3 = xr[384 + k];
        a0.x += x0 * w.x; a0.y += x0 * w.y; a0.z += x0 * w.z; a0.w += x0 * w.w;
        a1.x += x1 * w.x; a1.y += x1 * w.y; a1.z += x1 * w.z; a1.w += x1 * w.w;
        a2.x += x2 * w.x; a2.y += x2 * w.y; a2.z += x2 * w.z; a2.w += x2 * w.w;
        a3.x += x3 * w.x; a3.y += x3 * w.y; a3.z += x3 * w.z; a3.w += x3 * w.w;
    }

    float4 s4 = __ldg((const float4*)(attS + lane * 4));
    float4 d4 = __ldg((const float4*)(attD + lane * 4));
    float4 accs[4] = {a0, a1, a2, a3};
    #pragma unroll
    for (int r = 0; r < 4; r++) {
        int gr = row0 + ry * 4 + r;
        if (gr >= N) continue;
        float4 a = accs[r];
        // fp16 store (messages only; logits stay fp32)
        __half2 h_lo = __floats2half2_rn(a.x, a.y);
        __half2 h_hi = __floats2half2_rn(a.z, a.w);
        uint2 packed = make_uint2(*(unsigned*)&h_lo, *(unsigned*)&h_hi);
        *(uint2*)(g_h1h + (size_t)gr * 128 + lane * 4) = packed;

        float ps = a.x * s4.x + a.y * s4.y + a.z * s4.z + a.w * s4.w;
        float pd = a.x * d4.x + a.y * d4.y + a.z * d4.z + a.w * d4.w;
        #pragma unroll
        for (int off = 8; off > 0; off >>= 1) {
            ps += __shfl_down_sync(0xffffffffu, ps, off, 16);
            pd += __shfl_down_sync(0xffffffffu, pd, off, 16);
        }
        if (lane == 0)  { g_as1[gr * 2 + 0] = ps; g_ad1[gr * 2 + 0] = pd; }
        if (lane == 16) { g_as1[gr * 2 + 1] = ps; g_ad1[gr * 2 + 1] = pd; }
    }
}

// ---------------- kernel 2: dst histogram ----------------
__global__ void hist_kernel(const int* __restrict__ ei, int N, int E) {
    int e = blockIdx.x * blockDim.x + threadIdx.x;
    int E2 = E + N;
    if (e < E2) {
        int d = (e < E) ? ei[E + e] : (e - E);
        atomicAdd(&g_cnt[d], 1);
    }
}

// ---------------- scan phase A: per-block inclusive scan + block sums ----------------
__global__ void scan_blocks_kernel(int N) {
    __shared__ int warp_sums[32];
    int tid = threadIdx.x;
    int lane = tid & 31, wid = tid >> 5;
    int i = blockIdx.x * SCAN_B + tid;
    int v = (i < N) ? g_cnt[i] : 0;
    int xv = v;
    #pragma unroll
    for (int off = 1; off < 32; off <<= 1) {
        int y = __shfl_up_sync(0xffffffffu, xv, off);
        if (lane >= off) xv += y;
    }
    if (lane == 31) warp_sums[wid] = xv;
    __syncthreads();
    if (wid == 0) {
        int s = warp_sums[lane];
        #pragma unroll
        for (int off = 1; off < 32; off <<= 1) {
            int y = __shfl_up_sync(0xffffffffu, s, off);
            if (lane >= off) s += y;
        }
        warp_sums[lane] = s;
    }
    __syncthreads();
    int pre = (wid > 0) ? warp_sums[wid - 1] : 0;
    int incl = xv + pre;                 // block-local inclusive
    if (i < N) g_rowptr[i + 1] = incl;
    if (tid == SCAN_B - 1) g_bsum[blockIdx.x] = incl;
}

// ---------------- scan phase B: exclusive scan of block sums (tiny) ----------------
__global__ void scan_top_kernel(int nb) {
    if (threadIdx.x == 0) {
        int run = 0;
        for (int b = 0; b < nb; b++) {
            int v = g_bsum[b];
            g_bsum[b] = run;
            run += v;
        }
    }
}

// ---------------- scan phase C: add block offsets ----------------
__global__ void scan_add_kernel(int N) {
    int i = blockIdx.x * blockDim.x + threadIdx.x;
    if (i < N) g_rowptr[i + 1] += g_bsum[i >> 10];
}

// ---------------- kernel 4: scatter edges into CSR (by dst) ----------------
__global__ void scatter_kernel(const int* __restrict__ ei, int N, int E) {
    int e = blockIdx.x * blockDim.x + threadIdx.x;
    int E2 = E + N;
    if (e < E2) {
        int s, d;
        if (e < E) { s = ei[e]; d = ei[E + e]; }
        else       { s = e - E; d = s; }
        int slot = g_rowptr[d] + atomicAdd(&g_fill[d], 1);
        g_col[slot] = s;
    }
}

// ---------------- kernel 5: layer-1 softmax aggregation (warp per dst) ----------------
__global__ void agg1_kernel(const float* __restrict__ bias1, int N) {
    int wid = threadIdx.x >> 5;
    int lane = threadIdx.x & 31;
    int d = blockIdx.x * 8 + wid;
    if (d >= N) return;
    int p0 = g_rowptr[d], p1 = g_rowptr[d + 1];

    float2 adv = *(const float2*)(g_ad1 + d * 2);
    float my_ad = (lane < 16) ? adv.x : adv.y;

    float m = -1e30f, den = 0.f;
    float4 acc = make_float4(0,0,0,0);
    for (int e = p0; e < p1; e++) {
        int s = g_col[e];
        float2 asv = *(const float2*)(g_as1 + s * 2);
        float logit = ((lane < 16) ? asv.x : asv.y) + my_ad;
        logit = (logit > 0.f) ? logit : 0.2f * logit;
        float mnew = fmaxf(m, logit);
        float scale = __expf(m - mnew);
        float ev = __expf(logit - mnew);
        uint2 hp = *(const uint2*)(g_h1h + (size_t)s * 128 + lane * 4);
        float2 lo = __half22float2(*(__half2*)&hp.x);
        float2 hi = __half22float2(*(__half2*)&hp.y);
        den = den * scale + ev;
        acc.x = acc.x * scale + ev * lo.x;
        acc.y = acc.y * scale + ev * lo.y;
        acc.z = acc.z * scale + ev * hi.x;
        acc.w = acc.w * scale + ev * hi.y;
        m = mnew;
    }
    float inv = 1.f / (den + 1e-16f);
    float4 b = __ldg((const float4*)(bias1 + lane * 4));
    float4 o;
    o.x = fmaxf(acc.x * inv + b.x, 0.f);
    o.y = fmaxf(acc.y * inv + b.y, 0.f);
    o.z = fmaxf(acc.z * inv + b.z, 0.f);
    o.w = fmaxf(acc.w * inv + b.w, 0.f);
    *(float4*)(g_hr + (size_t)d * 128 + lane * 4) = o;
}

// ---------------- kernel 6: h2 = hr@W2, plus attention dots (H=1,C=32) ----------------
__global__ void gemm2_kernel(const float* __restrict__ W2,
                             const float* __restrict__ attS2, const float* __restrict__ attD2,
                             int N) {
    __shared__ float W2s[128 * 32];
    int tid = threadIdx.x;
    for (int i = tid; i < 128 * 32 / 4; i += 256)
        ((float4*)W2s)[i] = __ldg(((const float4*)W2) + i);
    __syncthreads();

    int lane = tid & 31, wid = tid >> 5;
    int row = blockIdx.x * 8 + wid;
    if (row >= N) return;
    const float* hr = g_hr + (size_t)row * 128;
    float f0 = hr[lane], f1 = hr[32 + lane], f2 = hr[64 + lane], f3 = hr[96 + lane];
    float acc = 0.f;
    #pragma unroll
    for (int k = 0; k < 32; k++) {
        acc += __shfl_sync(0xffffffffu, f0, k) * W2s[k * 32 + lane];
        acc += __shfl_sync(0xffffffffu, f1, k) * W2s[(k + 32) * 32 + lane];
        acc += __shfl_sync(0xffffffffu, f2, k) * W2s[(k + 64) * 32 + lane];
        acc += __shfl_sync(0xffffffffu, f3, k) * W2s[(k + 96) * 32 + lane];
    }
    g_h2[(size_t)row * 32 + lane] = acc;
    float ps = acc * __ldg(attS2 + lane);
    float pd = acc * __ldg(attD2 + lane);
    #pragma unroll
    for (int off = 16; off > 0; off >>= 1) {
        ps += __shfl_down_sync(0xffffffffu, ps, off);
        pd += __shfl_down_sync(0xffffffffu, pd, off);
    }
    if (lane == 0) { g_as2[row] = ps; g_ad2[row] = pd; }
}

// ---------------- kernel 7: layer-2 softmax aggregation (warp per dst) ----------------
__global__ void agg2_kernel(const float* __restrict__ bias2, float* __restrict__ out, int N) {
    int wid = threadIdx.x >> 5;
    int lane = threadIdx.x & 31;
    int d = blockIdx.x * 8 + wid;
    if (d >= N) return;
    int p0 = g_rowptr[d], p1 = g_rowptr[d + 1];
    float add = g_ad2[d];

    float m = -1e30f, den = 0.f, acc = 0.f;
    for (int e = p0; e < p1; e++) {
        int s = g_col[e];
        float logit = g_as2[s] + add;
        logit = (logit > 0.f) ? logit : 0.2f * logit;
        float mnew = fmaxf(m, logit);
        float scale = __expf(m - mnew);
        float ev = __expf(logit - mnew);
        float hv = g_h2[(size_t)s * 32 + lane];
        den = den * scale + ev;
        acc = acc * scale + ev * hv;
        m = mnew;
    }
    out[(size_t)d * 32 + lane] = acc / (den + 1e-16f) + __ldg(bias2 + lane);
}

// ---------------- launch ----------------
extern "C" void kernel_launch(void* const* d_in, const int* in_sizes, int n_in,
                              void* d_out, int out_size) {
    const float* x      = (const float*)d_in[0];
    const int*   ei     = (const int*)  d_in[1];
    const float* W1     = (const float*)d_in[2];
    const float* attS1  = (const float*)d_in[3];
    const float* attD1  = (const float*)d_in[4];
    const float* bias1  = (const float*)d_in[5];
    const float* W2     = (const float*)d_in[6];
    const float* attS2  = (const float*)d_in[7];
    const float* attD2  = (const float*)d_in[8];
    const float* bias2  = (const float*)d_in[9];
    float* out = (float*)d_out;

    int N = in_sizes[0] / IN_DIM;
    int E = in_sizes[1] / 2;
    int E2 = E + N;
    int nb = (N + SCAN_B - 1) / SCAN_B;

    zero_kernel<<<(N + 255) / 256, 256>>>(N);
    gemm1_kernel<<<(N + G1_ROWS - 1) / G1_ROWS, 256>>>(x, W1, attS1, attD1, N);
    hist_kernel<<<(E2 + 255) / 256, 256>>>(ei, N, E);
    scan_blocks_kernel<<<nb, SCAN_B>>>(N);
    scan_top_kernel<<<1, 32>>>(nb);
    scan_add_kernel<<<(N + 255) / 256, 256>>>(N);
    scatter_kernel<<<(E2 + 255) / 256, 256>>>(ei, N, E);
    agg1_kernel<<<(N + 7) / 8, 256>>>(bias1, N);
    gemm2_kernel<<<(N + 7) / 8, 256>>>(W2, attS2, attD2, N);
    agg2_kernel<<<(N + 7) / 8, 256>>>(bias2, out, N);
}

// round 7
// speedup vs baseline: 1.3307x; 1.1499x over previous
#include <cuda_runtime.h>
#include <cuda_fp16.h>
#include <cuda_bf16.h>
#include <math_constants.h>

// Problem constants (from reference setup_inputs)
#define MAXN 50000
#define MAXE 800000
#define MAXE2 (MAXN + MAXE)
#define IN_DIM 128
#define F1 128      // H1*HID = 2*64
#define HID 64
#define OUT_DIM 32
#define SCAN_B 1024
#define NBLK ((MAXN + SCAN_B - 1) / SCAN_B)

// ---------------- scratch (static device globals; no allocation) ----------------
__device__ __half g_h1h[(size_t)MAXN * F1];    // layer1 pre-agg features (x@W1), fp16
__device__ __half g_h2h[(size_t)MAXN * OUT_DIM]; // layer2 pre-agg features, fp16
__device__ float g_as1[MAXN * 2];
__device__ float g_ad1[MAXN * 2];
__device__ float g_as2[MAXN];
__device__ float g_ad2[MAXN];
__device__ int   g_cnt[MAXN];
__device__ int   g_fill[MAXN];
__device__ int   g_rowptr[MAXN + 1];
__device__ int   g_bsum[64];
__device__ int   g_col[MAXE2];                 // src node id, edges grouped by dst

// ---------------- kernel 0: zero counters ----------------
__global__ void zero_kernel(int N) {
    int i = blockIdx.x * blockDim.x + threadIdx.x;
    if (i < N) { g_cnt[i] = 0; g_fill[i] = 0; }
    if (i == 0) g_rowptr[0] = 0;
}

// ---------------- kernel 1: h1 = x@W1 (fp16 out), plus per-node attention dots ----------------
#define G1_ROWS 32
__global__ void gemm1_kernel(const float* __restrict__ x, const float* __restrict__ W1,
                             const float* __restrict__ attS, const float* __restrict__ attD,
                             int N) {
    __shared__ float xs[G1_ROWS * 128];
    int row0 = blockIdx.x * G1_ROWS;
    int tid = threadIdx.x;
    for (int i = tid; i < G1_ROWS * 128 / 4; i += 256) {
        int elt = i * 4;
        int r = elt >> 7;
        int c = elt & 127;
        int gr = row0 + r;
        float4 v = make_float4(0.f, 0.f, 0.f, 0.f);
        if (gr < N) v = *(const float4*)(x + (size_t)gr * 128 + c);
        *(float4*)(xs + elt) = v;
    }
    __syncthreads();

    int lane = tid & 31;
    int ry = tid >> 5;
    const float* Wc = W1 + lane * 4;
    const float* xr = xs + (ry * 4) * 128;

    float4 a0 = make_float4(0,0,0,0), a1 = a0, a2 = a0, a3 = a0;
    #pragma unroll 4
    for (int k = 0; k < 128; k++) {
        float4 w = __ldg((const float4*)(Wc + (size_t)k * 128));
        float x0 = xr[k], x1 = xr[128 + k], x2 = xr[256 + k], x3 = xr[384 + k];
        a0.x += x0 * w.x; a0.y += x0 * w.y; a0.z += x0 * w.z; a0.w += x0 * w.w;
        a1.x += x1 * w.x; a1.y += x1 * w.y; a1.z += x1 * w.z; a1.w += x1 * w.w;
        a2.x += x2 * w.x; a2.y += x2 * w.y; a2.z += x2 * w.z; a2.w += x2 * w.w;
        a3.x += x3 * w.x; a3.y += x3 * w.y; a3.z += x3 * w.z; a3.w += x3 * w.w;
    }

    float4 s4 = __ldg((const float4*)(attS + lane * 4));
    float4 d4 = __ldg((const float4*)(attD + lane * 4));
    float4 accs[4] = {a0, a1, a2, a3};
    #pragma unroll
    for (int r = 0; r < 4; r++) {
        int gr = row0 + ry * 4 + r;
        if (gr >= N) continue;
        float4 a = accs[r];
        __half2 h_lo = __floats2half2_rn(a.x, a.y);
        __half2 h_hi = __floats2half2_rn(a.z, a.w);
        uint2 packed = make_uint2(*(unsigned*)&h_lo, *(unsigned*)&h_hi);
        *(uint2*)(g_h1h + (size_t)gr * 128 + lane * 4) = packed;

        float ps = a.x * s4.x + a.y * s4.y + a.z * s4.z + a.w * s4.w;
        float pd = a.x * d4.x + a.y * d4.y + a.z * d4.z + a.w * d4.w;
        #pragma unroll
        for (int off = 8; off > 0; off >>= 1) {
            ps += __shfl_down_sync(0xffffffffu, ps, off, 16);
            pd += __shfl_down_sync(0xffffffffu, pd, off, 16);
        }
        if (lane == 0)  { g_as1[gr * 2 + 0] = ps; g_ad1[gr * 2 + 0] = pd; }
        if (lane == 16) { g_as1[gr * 2 + 1] = ps; g_ad1[gr * 2 + 1] = pd; }
    }
}

// ---------------- kernel 2: dst histogram ----------------
__global__ void hist_kernel(const int* __restrict__ ei, int N, int E) {
    int e = blockIdx.x * blockDim.x + threadIdx.x;
    int E2 = E + N;
    if (e < E2) {
        int d = (e < E) ? ei[E + e] : (e - E);
        atomicAdd(&g_cnt[d], 1);
    }
}

// ---------------- scan phase A: per-block inclusive scan + block sums ----------------
__global__ void scan_blocks_kernel(int N) {
    __shared__ int warp_sums[32];
    int tid = threadIdx.x;
    int lane = tid & 31, wid = tid >> 5;
    int i = blockIdx.x * SCAN_B + tid;
    int v = (i < N) ? g_cnt[i] : 0;
    int xv = v;
    #pragma unroll
    for (int off = 1; off < 32; off <<= 1) {
        int y = __shfl_up_sync(0xffffffffu, xv, off);
        if (lane >= off) xv += y;
    }
    if (lane == 31) warp_sums[wid] = xv;
    __syncthreads();
    if (wid == 0) {
        int s = warp_sums[lane];
        #pragma unroll
        for (int off = 1; off < 32; off <<= 1) {
            int y = __shfl_up_sync(0xffffffffu, s, off);
            if (lane >= off) s += y;
        }
        warp_sums[lane] = s;
    }
    __syncthreads();
    int pre = (wid > 0) ? warp_sums[wid - 1] : 0;
    int incl = xv + pre;
    if (i < N) g_rowptr[i + 1] = incl;
    if (tid == SCAN_B - 1) g_bsum[blockIdx.x] = incl;
}

// ---------------- scan phase B: parallel exclusive scan of <=64 block sums ----------------
__global__ void scan_top_kernel(int nb) {
    __shared__ int sh[64];
    int t = threadIdx.x;
    int v = (t < nb) ? g_bsum[t] : 0;
    sh[t] = v;
    __syncthreads();
    #pragma unroll
    for (int off = 1; off < 64; off <<= 1) {
        int y = (t >= off) ? sh[t - off] : 0;
        __syncthreads();
        sh[t] += y;
        __syncthreads();
    }
    if (t < nb) g_bsum[t] = sh[t] - v;   // exclusive
}

// ---------------- scan phase C: add block offsets ----------------
__global__ void scan_add_kernel(int N) {
    int i = blockIdx.x * blockDim.x + threadIdx.x;
    if (i < N) g_rowptr[i + 1] += g_bsum[i >> 10];
}

// ---------------- kernel 4: scatter edges into CSR (by dst) ----------------
__global__ void scatter_kernel(const int* __restrict__ ei, int N, int E) {
    int e = blockIdx.x * blockDim.x + threadIdx.x;
    int E2 = E + N;
    if (e < E2) {
        int s, d;
        if (e < E) { s = ei[e]; d = ei[E + e]; }
        else       { s = e - E; d = s; }
        int slot = g_rowptr[d] + atomicAdd(&g_fill[d], 1);
        g_col[slot] = s;
    }
}

// ---------------- kernel 5: layer-1 softmax agg + fused gemm2 + layer-2 dots ----------------
// warp per dst. Online softmax over incoming edges, 4x software pipelined.
__device__ __forceinline__ void agg1_update(float asv, float my_ad, uint2 hp,
                                            float& m, float& den, float4& acc) {
    float logit = asv + my_ad;
    logit = (logit > 0.f) ? logit : 0.2f * logit;
    float mnew = fmaxf(m, logit);
    float scale = __expf(m - mnew);
    float ev = __expf(logit - mnew);
    float2 lo = __half22float2(*(__half2*)&hp.x);
    float2 hi = __half22float2(*(__half2*)&hp.y);
    den = den * scale + ev;
    acc.x = acc.x * scale + ev * lo.x;
    acc.y = acc.y * scale + ev * lo.y;
    acc.z = acc.z * scale + ev * hi.x;
    acc.w = acc.w * scale + ev * hi.y;
    m = mnew;
}

__global__ void agg1_kernel(const float* __restrict__ bias1, const float* __restrict__ W2,
                            const float* __restrict__ attS2, const float* __restrict__ attD2,
                            int N) {
    __shared__ float W2s[128 * 32];
    int tid = threadIdx.x;
    for (int i = tid; i < 128 * 32 / 4; i += 256)
        ((float4*)W2s)[i] = __ldg(((const float4*)W2) + i);
    __syncthreads();

    int wid = tid >> 5;
    int lane = tid & 31;
    int d = blockIdx.x * 8 + wid;
    if (d >= N) return;
    int p0 = g_rowptr[d], p1 = g_rowptr[d + 1];

    float2 adv = *(const float2*)(g_ad1 + d * 2);
    float my_ad = (lane < 16) ? adv.x : adv.y;
    bool head0 = (lane < 16);

    float m = -1e30f, den = 0.f;
    float4 acc = make_float4(0, 0, 0, 0);
    const __half* h1base = g_h1h;
    int e = p0;
    for (; e + 4 <= p1; e += 4) {
        int s0 = g_col[e], s1 = g_col[e + 1], s2 = g_col[e + 2], s3 = g_col[e + 3];
        float2 av0 = *(const float2*)(g_as1 + s0 * 2);
        float2 av1 = *(const float2*)(g_as1 + s1 * 2);
        float2 av2 = *(const float2*)(g_as1 + s2 * 2);
        float2 av3 = *(const float2*)(g_as1 + s3 * 2);
        uint2 q0 = *(const uint2*)(h1base + (size_t)s0 * 128 + lane * 4);
        uint2 q1 = *(const uint2*)(h1base + (size_t)s1 * 128 + lane * 4);
        uint2 q2 = *(const uint2*)(h1base + (size_t)s2 * 128 + lane * 4);
        uint2 q3 = *(const uint2*)(h1base + (size_t)s3 * 128 + lane * 4);
        agg1_update(head0 ? av0.x : av0.y, my_ad, q0, m, den, acc);
        agg1_update(head0 ? av1.x : av1.y, my_ad, q1, m, den, acc);
        agg1_update(head0 ? av2.x : av2.y, my_ad, q2, m, den, acc);
        agg1_update(head0 ? av3.x : av3.y, my_ad, q3, m, den, acc);
    }
    for (; e < p1; e++) {
        int s = g_col[e];
        float2 av = *(const float2*)(g_as1 + s * 2);
        uint2 q = *(const uint2*)(h1base + (size_t)s * 128 + lane * 4);
        agg1_update(head0 ? av.x : av.y, my_ad, q, m, den, acc);
    }

    float inv = 1.f / (den + 1e-16f);
    float4 b = __ldg((const float4*)(bias1 + lane * 4));
    float4 o;
    o.x = fmaxf(acc.x * inv + b.x, 0.f);
    o.y = fmaxf(acc.y * inv + b.y, 0.f);
    o.z = fmaxf(acc.z * inv + b.z, 0.f);
    o.w = fmaxf(acc.w * inv + b.w, 0.f);

    // fused gemm2: hr row (o spread across warp, lane holds cols 4*lane..4*lane+3)
    float acc2 = 0.f;
    #pragma unroll 8
    for (int k = 0; k < 32; k++) {
        float bx = __shfl_sync(0xffffffffu, o.x, k);
        float by = __shfl_sync(0xffffffffu, o.y, k);
        float bz = __shfl_sync(0xffffffffu, o.z, k);
        float bw = __shfl_sync(0xffffffffu, o.w, k);
        acc2 += bx * W2s[(4 * k + 0) * 32 + lane]
              + by * W2s[(4 * k + 1) * 32 + lane]
              + bz * W2s[(4 * k + 2) * 32 + lane]
              + bw * W2s[(4 * k + 3) * 32 + lane];
    }
    g_h2h[(size_t)d * 32 + lane] = __float2half(acc2);

    float ps = acc2 * __ldg(attS2 + lane);
    float pd = acc2 * __ldg(attD2 + lane);
    #pragma unroll
    for (int off = 16; off > 0; off >>= 1) {
        ps += __shfl_down_sync(0xffffffffu, ps, off);
        pd += __shfl_down_sync(0xffffffffu, pd, off);
    }
    if (lane == 0) { g_as2[d] = ps; g_ad2[d] = pd; }
}

// ---------------- kernel 7: layer-2 softmax aggregation (warp per dst, 4x pipelined) ----------------
__device__ __forceinline__ void agg2_update(float as, float add, float hv,
                                            float& m, float& den, float& acc) {
    float logit = as + add;
    logit = (logit > 0.f) ? logit : 0.2f * logit;
    float mnew = fmaxf(m, logit);
    float scale = __expf(m - mnew);
    float ev = __expf(logit - mnew);
    den = den * scale + ev;
    acc = acc * scale + ev * hv;
    m = mnew;
}

__global__ void agg2_kernel(const float* __restrict__ bias2, float* __restrict__ out, int N) {
    int wid = threadIdx.x >> 5;
    int lane = threadIdx.x & 31;
    int d = blockIdx.x * 8 + wid;
    if (d >= N) return;
    int p0 = g_rowptr[d], p1 = g_rowptr[d + 1];
    float add = g_ad2[d];

    float m = -1e30f, den = 0.f, acc = 0.f;
    int e = p0;
    for (; e + 4 <= p1; e += 4) {
        int s0 = g_col[e], s1 = g_col[e + 1], s2 = g_col[e + 2], s3 = g_col[e + 3];
        float a0 = g_as2[s0], a1 = g_as2[s1], a2 = g_as2[s2], a3 = g_as2[s3];
        float h0 = __half2float(g_h2h[(size_t)s0 * 32 + lane]);
        float h1 = __half2float(g_h2h[(size_t)s1 * 32 + lane]);
        float h2 = __half2float(g_h2h[(size_t)s2 * 32 + lane]);
        float h3 = __half2float(g_h2h[(size_t)s3 * 32 + lane]);
        agg2_update(a0, add, h0, m, den, acc);
        agg2_update(a1, add, h1, m, den, acc);
        agg2_update(a2, add, h2, m, den, acc);
        agg2_update(a3, add, h3, m, den, acc);
    }
    for (; e < p1; e++) {
        int s = g_col[e];
        float a = g_as2[s];
        float hv = __half2float(g_h2h[(size_t)s * 32 + lane]);
        agg2_update(a, add, hv, m, den, acc);
    }
    out[(size_t)d * 32 + lane] = acc / (den + 1e-16f) + __ldg(bias2 + lane);
}

// ---------------- launch ----------------
extern "C" void kernel_launch(void* const* d_in, const int* in_sizes, int n_in,
                              void* d_out, int out_size) {
    const float* x      = (const float*)d_in[0];
    const int*   ei     = (const int*)  d_in[1];
    const float* W1     = (const float*)d_in[2];
    const float* attS1  = (const float*)d_in[3];
    const float* attD1  = (const float*)d_in[4];
    const float* bias1  = (const float*)d_in[5];
    const float* W2     = (const float*)d_in[6];
    const float* attS2  = (const float*)d_in[7];
    const float* attD2  = (const float*)d_in[8];
    const float* bias2  = (const float*)d_in[9];
    float* out = (float*)d_out;

    int N = in_sizes[0] / IN_DIM;
    int E = in_sizes[1] / 2;
    int E2 = E + N;
    int nb = (N + SCAN_B - 1) / SCAN_B;

    zero_kernel<<<(N + 255) / 256, 256>>>(N);
    gemm1_kernel<<<(N + G1_ROWS - 1) / G1_ROWS, 256>>>(x, W1, attS1, attD1, N);
    hist_kernel<<<(E2 + 255) / 256, 256>>>(ei, N, E);
    scan_blocks_kernel<<<nb, SCAN_B>>>(N);
    scan_top_kernel<<<1, 64>>>(nb);
    scan_add_kernel<<<(N + 255) / 256, 256>>>(N);
    scatter_kernel<<<(E2 + 255) / 256, 256>>>(ei, N, E);
    agg1_kernel<<<(N + 7) / 8, 256>>>(bias1, W2, attS2, attD2, N);
    agg2_kernel<<<(N + 7) / 8, 256>>>(bias2, out, N);
}